// round 8
// baseline (speedup 1.0000x reference)
#include <cuda_runtime.h>
#include <cstdint>

#define SQ   256
#define NH   16
#define HD   64
#define HIDW 1024
#define LOG2E 1.4426950408889634f

static __device__ float  g_Q[NH*SQ*HD];
static __device__ float  g_K[NH*SQ*HD];
static __device__ float  g_V[NH*SQ*HD];
static __device__ float  g_S[NH*SQ*SQ];
static __device__ float  g_P[NH*SQ*SQ];
static __device__ float2 g_AP[NH*SQ*SQ];
static __device__ float  g_P2[NH*SQ];
static __device__ float  g_Ctx[SQ*HIDW];
static __device__ float  g_Part[NH*SQ*HD];     // [row][d]

__device__ __forceinline__ float ex2f(float x){ float y; asm("ex2.approx.ftz.f32 %0, %1;" : "=f"(y) : "f"(x)); return y; }
__device__ __forceinline__ float rcpf(float x){ float y; asm("rcp.approx.ftz.f32 %0, %1;" : "=f"(y) : "f"(x)); return y; }
__device__ __forceinline__ uint32_t f2tf32(float x){ uint32_t r; asm("cvt.rna.tf32.f32 %0, %1;" : "=r"(r) : "f"(x)); return r; }

__device__ __forceinline__ void mma8(float* c, const uint32_t* a, const uint32_t* b){
    asm volatile("mma.sync.aligned.m16n8k8.row.col.f32.tf32.tf32.f32 "
        "{%0,%1,%2,%3}, {%4,%5,%6,%7}, {%8,%9}, {%0,%1,%2,%3};"
        : "+f"(c[0]), "+f"(c[1]), "+f"(c[2]), "+f"(c[3])
        : "r"(a[0]), "r"(a[1]), "r"(a[2]), "r"(a[3]), "r"(b[0]), "r"(b[1]));
}

// ---------------------------------------------------------------------------
// tf32-split GEMM: D[(64*MT) x 64] = A[(64*MT) x KT] * B(k-major)[KT x 64]
// 3-term split (hi*hi + hi*lo + lo*hi) => fp32-grade accuracy on tensor cores.
// MODE 0: fused = hidden @ Wqkv (+bias) -> scatter Q/K/V   [B = Wqkv, direct]
// MODE 1: S[h]  = Q[h] @ K[h]^T                            [B = K, transposed at staging]
// MODE 2: Ctx   = P[h] @ V[h]                              [B = V, direct]
// MODE 3: out   = Ctx @ Wd (+bias+residual)                [B = Wd, direct]
// ---------------------------------------------------------------------------
#define BSZ (32*72)

template<int MODE, int MT>
__global__ void __launch_bounds__(256, 1) mma_gemm(const float* __restrict__ Aext,
                                                   const float* __restrict__ Bext,
                                                   const float* __restrict__ bias,
                                                   const float* __restrict__ resid,
                                                   float* __restrict__ outp)
{
    constexpr int KT  = (MODE==1) ? 64 : (MODE==2) ? 256 : 1024;
    constexpr int NK  = KT/32;
    constexpr int LDA = (MODE==1) ? 64 : (MODE==2) ? 256 : 1024;
    constexpr int LDB = (MODE==0) ? 3072 : (MODE==1) ? 64 : (MODE==2) ? 64 : 1024;
    constexpr int BM  = 64*MT;
    constexpr int AST = BM + 8;
    constexpr int ASZ = 32*AST;

    extern __shared__ float sm[];
    float* Ah = sm;
    float* Al = sm + ASZ;
    float* Bh = sm + 2*ASZ;
    float* Bl = sm + 2*ASZ + BSZ;
    const uint32_t* Ahu = (const uint32_t*)Ah;
    const uint32_t* Alu = (const uint32_t*)Al;
    const uint32_t* Bhu = (const uint32_t*)Bh;
    const uint32_t* Blu = (const uint32_t*)Bl;

    const int tid = threadIdx.x, lane = tid & 31, wid = tid >> 5;
    const int wm = wid >> 1, wn = wid & 1;
    const int tig = lane & 3, gid = lane >> 2;
    const int n0 = blockIdx.x*64, m0 = blockIdx.y*BM, z = blockIdx.z;

    const float* Ag; const float* Bg;
    if constexpr (MODE==0)      { Ag = Aext;                      Bg = Bext; }
    else if constexpr (MODE==1) { Ag = g_Q + z*SQ*HD;             Bg = g_K + z*SQ*HD; }
    else if constexpr (MODE==2) { Ag = g_P + (size_t)z*SQ*SQ;     Bg = g_V + z*SQ*HD; }
    else                        { Ag = g_Ctx;                     Bg = Bext; }

    const int kqw = tid & 3, mrw = (tid >> 2) & 7, aw = tid >> 5;
    float4 pa[2*MT]; float4 pb[2]; float pbt[8];

    auto loadA = [&](int kt){
#pragma unroll
        for (int mi = 0; mi < MT; mi++)
#pragma unroll
            for (int ki = 0; ki < 2; ki++) {
                int m = aw*8 + mrw + 64*mi, kq = kqw + 4*ki;
                pa[mi*2+ki] = *(const float4*)(Ag + (size_t)(m0+m)*LDA + kt*32 + kq*4);
            }
    };
    auto loadB = [&](int kt){
        if constexpr (MODE==1) {
            int d = tid & 31, jb = (tid >> 5) * 8;
#pragma unroll
            for (int r = 0; r < 8; r++)
                pbt[r] = Bg[(size_t)(n0 + jb + r)*LDB + kt*32 + d];
        } else {
#pragma unroll
            for (int r = 0; r < 2; r++) {
                int idx = tid + 256*r, kr = idx >> 4, nq = idx & 15;
                pb[r] = *(const float4*)(Bg + (size_t)(kt*32 + kr)*LDB + n0 + nq*4);
            }
        }
    };
    auto stage = [&](){
#pragma unroll
        for (int mi = 0; mi < MT; mi++)
#pragma unroll
            for (int ki = 0; ki < 2; ki++) {
                int m = aw*8 + mrw + 64*mi, kq = kqw + 4*ki;
                int mb = m ^ ((kq & 3) << 3);
                float4 v = pa[mi*2+ki];
                float vv[4] = {v.x, v.y, v.z, v.w};
#pragma unroll
                for (int e = 0; e < 4; e++) {
                    uint32_t hb = f2tf32(vv[e]);
                    float hf = __uint_as_float(hb);
                    uint32_t lb = f2tf32(vv[e] - hf);
                    Ah[(kq*4+e)*AST + mb] = hf;
                    Al[(kq*4+e)*AST + mb] = __uint_as_float(lb);
                }
            }
        if constexpr (MODE==1) {
            int d = tid & 31, jb = (tid >> 5) * 8;
            int C = ((d >> 2) & 3) << 3;
#pragma unroll
            for (int r = 0; r < 8; r++) {
                uint32_t hb = f2tf32(pbt[r]);
                float hf = __uint_as_float(hb);
                uint32_t lb = f2tf32(pbt[r] - hf);
                int off = d*72 + ((jb + r) ^ C);
                Bh[off] = hf; Bl[off] = __uint_as_float(lb);
            }
        } else {
#pragma unroll
            for (int r = 0; r < 2; r++) {
                int idx = tid + 256*r, kr = idx >> 4, nq = idx & 15;
                int off = kr*72 + ((nq*4) ^ (((kr >> 2) & 3) << 3));
                float4 v = pb[r];
                float4 h4, l4;
                uint32_t b;
                b = f2tf32(v.x); h4.x = __uint_as_float(b); l4.x = __uint_as_float(f2tf32(v.x - h4.x));
                b = f2tf32(v.y); h4.y = __uint_as_float(b); l4.y = __uint_as_float(f2tf32(v.y - h4.y));
                b = f2tf32(v.z); h4.z = __uint_as_float(b); l4.z = __uint_as_float(f2tf32(v.z - h4.z));
                b = f2tf32(v.w); h4.w = __uint_as_float(b); l4.w = __uint_as_float(f2tf32(v.w - h4.w));
                *(float4*)(Bh + off) = h4;
                *(float4*)(Bl + off) = l4;
            }
        }
    };

    float acc[MT][4][4];
#pragma unroll
    for (int a = 0; a < MT; a++)
#pragma unroll
        for (int b = 0; b < 4; b++)
#pragma unroll
            for (int c = 0; c < 4; c++) acc[a][b][c] = 0.f;

    loadA(0); loadB(0);

    for (int kt = 0; kt < NK; kt++) {
        __syncthreads();
        stage();
        __syncthreads();
        int ktn = (kt + 1 < NK) ? kt + 1 : kt;
        loadA(ktn); loadB(ktn);

#pragma unroll
        for (int ks = 0; ks < 4; ks++) {
            uint32_t ah[MT][4], al2[MT][4], bh[4][2], bl2[4][2];
            const int kA = ks*8 + tig;
            const int C0 = ((kA >> 2) & 3) << 3;
            const int C1 = (((kA + 4) >> 2) & 3) << 3;
#pragma unroll
            for (int mt = 0; mt < MT; mt++) {
                int m = wm*(16*MT) + mt*16 + gid;
                int mxa = m ^ C0, mya = m ^ C1;
                int i0 = kA*AST, i1 = (kA+4)*AST;
                ah[mt][0]  = Ahu[i0 + mxa];       ah[mt][1]  = Ahu[i0 + (mxa ^ 8)];
                ah[mt][2]  = Ahu[i1 + mya];       ah[mt][3]  = Ahu[i1 + (mya ^ 8)];
                al2[mt][0] = Alu[i0 + mxa];       al2[mt][1] = Alu[i0 + (mxa ^ 8)];
                al2[mt][2] = Alu[i1 + mya];       al2[mt][3] = Alu[i1 + (mya ^ 8)];
            }
#pragma unroll
            for (int nt = 0; nt < 4; nt++) {
                int n = wn*32 + nt*8 + gid;
                bh[nt][0]  = Bhu[kA*72 + (n ^ C0)];
                bh[nt][1]  = Bhu[(kA+4)*72 + (n ^ C1)];
                bl2[nt][0] = Blu[kA*72 + (n ^ C0)];
                bl2[nt][1] = Blu[(kA+4)*72 + (n ^ C1)];
            }
#pragma unroll
            for (int mt = 0; mt < MT; mt++)
#pragma unroll
                for (int nt = 0; nt < 4; nt++) {
                    mma8(acc[mt][nt], ah[mt],  bh[nt]);
                    mma8(acc[mt][nt], ah[mt],  bl2[nt]);
                    mma8(acc[mt][nt], al2[mt], bh[nt]);
                }
        }
    }

#pragma unroll
    for (int mt = 0; mt < MT; mt++) {
        int m = m0 + wm*(16*MT) + mt*16 + gid;
#pragma unroll
        for (int nt = 0; nt < 4; nt++) {
            int n = n0 + wn*32 + nt*8 + tig*2;
            float c0 = acc[mt][nt][0], c1 = acc[mt][nt][1];
            float c2 = acc[mt][nt][2], c3 = acc[mt][nt][3];
            if constexpr (MODE==0) {
                float2 bb = *(const float2*)(bias + n);
                int hh = n / 192, rem = n - hh*192, wch = rem >> 6, d = rem & 63;
                float* base = (wch == 0) ? g_Q : (wch == 1) ? g_K : g_V;
                *(float2*)(base + (size_t)(hh*SQ + m)*HD + d)     = make_float2(c0 + bb.x, c1 + bb.y);
                *(float2*)(base + (size_t)(hh*SQ + m + 8)*HD + d) = make_float2(c2 + bb.x, c3 + bb.y);
            } else if constexpr (MODE==1) {
                *(float2*)(g_S + (size_t)(z*SQ + m)*SQ + n)     = make_float2(c0, c1);
                *(float2*)(g_S + (size_t)(z*SQ + m + 8)*SQ + n) = make_float2(c2, c3);
            } else if constexpr (MODE==2) {
                *(float2*)(g_Ctx + (size_t)m*HIDW + z*HD + n)       = make_float2(c0, c1);
                *(float2*)(g_Ctx + (size_t)(m + 8)*HIDW + z*HD + n) = make_float2(c2, c3);
            } else {
                float2 bb = *(const float2*)(bias + n);
                float2 r0 = *(const float2*)(resid + (size_t)m*HIDW + n);
                float2 r1 = *(const float2*)(resid + (size_t)(m + 8)*HIDW + n);
                *(float2*)(outp + (size_t)m*HIDW + n)       = make_float2(c0 + bb.x + r0.x, c1 + bb.y + r0.y);
                *(float2*)(outp + (size_t)(m + 8)*HIDW + n) = make_float2(c2 + bb.x + r1.x, c3 + bb.y + r1.y);
            }
        }
    }
}

// ---------------------------------------------------------------------------
// Warp-per-row softmax: 8 warps/block, lane owns 8 j's, shfl-only reductions.
// Outputs p, A_j = exp(S/64) (masked), P2 = sum p^2.
// ---------------------------------------------------------------------------
__global__ void __launch_bounds__(256) softmax_k(const float* __restrict__ alibi,
                                                 const float* __restrict__ mask)
{
    const int w = threadIdx.x >> 5, ln = threadIdx.x & 31;
    const int row = blockIdx.x*8 + w;
    const int h = row >> 8, i = row & 255;
    const int j0 = ln*8;

    float4 s0 = *(const float4*)(g_S + (size_t)row*SQ + j0);
    float4 s1 = *(const float4*)(g_S + (size_t)row*SQ + j0 + 4);
    float4 a0 = *(const float4*)(alibi + h*SQ + j0);
    float4 a1 = *(const float4*)(alibi + h*SQ + j0 + 4);
    float4 k0 = *(const float4*)(mask + (size_t)i*SQ + j0);
    float4 k1 = *(const float4*)(mask + (size_t)i*SQ + j0 + 4);

    float sv[8] = {s0.x, s0.y, s0.z, s0.w, s1.x, s1.y, s1.z, s1.w};
    float al[8] = {a0.x, a0.y, a0.z, a0.w, a1.x, a1.y, a1.z, a1.w};
    float mk[8] = {k0.x, k0.y, k0.z, k0.w, k1.x, k1.y, k1.z, k1.w};

    float sc[8];
#pragma unroll
    for (int t = 0; t < 8; t++) sc[t] = fmaf(0.125f, sv[t], al[t]) + mk[t];

    float mx = sc[0];
#pragma unroll
    for (int t = 1; t < 8; t++) mx = fmaxf(mx, sc[t]);
#pragma unroll
    for (int o = 16; o; o >>= 1) mx = fmaxf(mx, __shfl_xor_sync(0xffffffffu, mx, o));

    float e[8], tot = 0.f;
#pragma unroll
    for (int t = 0; t < 8; t++) { e[t] = ex2f((sc[t] - mx) * LOG2E); tot += e[t]; }
#pragma unroll
    for (int o = 16; o; o >>= 1) tot += __shfl_xor_sync(0xffffffffu, tot, o);

    float iz = rcpf(tot);
    float p[8];
#pragma unroll
    for (int t = 0; t < 8; t++) p[t] = e[t] * iz;

    *(float4*)(g_P + (size_t)row*SQ + j0)     = make_float4(p[0], p[1], p[2], p[3]);
    *(float4*)(g_P + (size_t)row*SQ + j0 + 4) = make_float4(p[4], p[5], p[6], p[7]);

    float av[8];
#pragma unroll
    for (int t = 0; t < 8; t++) av[t] = (j0 + t <= i) ? ex2f(sv[t] * (LOG2E/64.f)) : 0.f;

    float4* app = (float4*)(g_AP + (size_t)row*SQ);
    app[ln*4 + 0] = make_float4(av[0], p[0], av[1], p[1]);
    app[ln*4 + 1] = make_float4(av[2], p[2], av[3], p[3]);
    app[ln*4 + 2] = make_float4(av[4], p[4], av[5], p[5]);
    app[ln*4 + 3] = make_float4(av[6], p[6], av[7], p[7]);

    float pq = 0.f;
#pragma unroll
    for (int t = 0; t < 8; t++) pq = fmaf(p[t], p[t], pq);
#pragma unroll
    for (int o = 16; o; o >>= 1) pq += __shfl_xor_sync(0xffffffffu, pq, o);
    if (ln == 0) g_P2[row] = pq;
}

// ---------------------------------------------------------------------------
// qk_importance: block = (pair(i1,255-i1), h), 256 threads = 2 j-parities x
// (2 rows x 64 d).  Parity halves per-thread trips (2x warps per block vs R7).
// Bounds rounded up to x4 exploiting g_AP[.].x == 0 for masked j.
// Partials combined in smem in fixed order (deterministic).
// ---------------------------------------------------------------------------
__global__ void __launch_bounds__(256) importance_k()
{
    __shared__ float s_red[6][2][128];
    const int tid = threadIdx.x;
    const int d   = tid & 63;
    const int p2  = (tid >> 6) & 1;
    const int par = tid >> 7;                 // j parity 0/1
    const int h   = blockIdx.y;
    const int i1  = blockIdx.x + 64*p2;       // 0..127
    const int i2  = 255 - i1;                 // 128..255
    const int row1 = h*SQ + i1, row2 = h*SQ + i2;

    const float qe1 = g_Q[row1*HD + d] * (-LOG2E/64.f);
    const float qe2 = g_Q[row2*HD + d] * (-LOG2E/64.f);
    const float*  kp  = g_K + h*SQ*HD + d;
    const float2* ap1 = g_AP + (size_t)row1*SQ;
    const float2* ap2 = g_AP + (size_t)row2*SQ;

    float Z1=0.f, W21=0.f, WP1=0.f, Z2=0.f, W22=0.f, WP2=0.f;
    const int e1 = (i1 + 4) & ~3;             // mult of 4, <= 128
    const int e2 = (i2 + 4) & ~3;             // mult of 4, <= 256
    int j = par;
    for (; j < e1; j += 4) {                  // phase 1: both rows, j and j+2
        float k0 = kp[j*HD],  k1 = kp[(j+2)*HD];
        float2 u0 = ap1[j], u1 = ap1[j+2];
        float2 v0 = ap2[j], v1 = ap2[j+2];
        float E0 = ex2f(qe1*k0), E1 = ex2f(qe1*k1);
        float F0 = ex2f(qe2*k0), F1 = ex2f(qe2*k1);
        float w;
        w = u0.x*E0; Z1 += w; W21 = fmaf(w,w,W21); WP1 = fmaf(w,u0.y,WP1);
        w = u1.x*E1; Z1 += w; W21 = fmaf(w,w,W21); WP1 = fmaf(w,u1.y,WP1);
        w = v0.x*F0; Z2 += w; W22 = fmaf(w,w,W22); WP2 = fmaf(w,v0.y,WP2);
        w = v1.x*F1; Z2 += w; W22 = fmaf(w,w,W22); WP2 = fmaf(w,v1.y,WP2);
    }
    for (; j < e2; j += 4) {                  // phase 2: row2 only
        float k0 = kp[j*HD],  k1 = kp[(j+2)*HD];
        float2 v0 = ap2[j], v1 = ap2[j+2];
        float F0 = ex2f(qe2*k0), F1 = ex2f(qe2*k1);
        float w;
        w = v0.x*F0; Z2 += w; W22 = fmaf(w,w,W22); WP2 = fmaf(w,v0.y,WP2);
        w = v1.x*F1; Z2 += w; W22 = fmaf(w,w,W22); WP2 = fmaf(w,v1.y,WP2);
    }

    const int slot = p2*64 + d;
    s_red[0][par][slot] = Z1;  s_red[1][par][slot] = W21; s_red[2][par][slot] = WP1;
    s_red[3][par][slot] = Z2;  s_red[4][par][slot] = W22; s_red[5][par][slot] = WP2;
    __syncthreads();
    if (tid < 128) {
        float Zt1 = s_red[0][0][tid] + s_red[0][1][tid];
        float Wt1 = s_red[1][0][tid] + s_red[1][1][tid];
        float Pt1 = s_red[2][0][tid] + s_red[2][1][tid];
        float Zt2 = s_red[3][0][tid] + s_red[3][1][tid];
        float Wt2 = s_red[4][0][tid] + s_red[4][1][tid];
        float Pt2 = s_red[5][0][tid] + s_red[5][1][tid];
        float iz1 = rcpf(Zt1), iz2 = rcpf(Zt2);
        g_Part[row1*HD + d] = fmaf(Wt1*iz1, iz1, -2.f*Pt1*iz1) + g_P2[row1];
        g_Part[row2*HD + d] = fmaf(Wt2*iz2, iz2, -2.f*Pt2*iz2) + g_P2[row2];
    }
}

// Single-kernel deterministic reduction: block per head.
__global__ void __launch_bounds__(256) reduce_imp(float* __restrict__ imp)
{
    __shared__ float s[4][64];
    const int h = blockIdx.x, rr = threadIdx.x >> 6, d = threadIdx.x & 63;
    float s0 = 0.f;
#pragma unroll 8
    for (int r = 0; r < 64; ++r)
        s0 += g_Part[(h*SQ + rr*64 + r)*HD + d];
    s[rr][d] = s0;
    __syncthreads();
    if (threadIdx.x < 64)
        imp[h*64 + threadIdx.x] = (s[0][threadIdx.x] + s[1][threadIdx.x])
                                + (s[2][threadIdx.x] + s[3][threadIdx.x]);
}

// ---------------------------------------------------------------------------
extern "C" void kernel_launch(void* const* d_in, const int* in_sizes, int n_in,
                              void* d_out, int out_size)
{
    (void)in_sizes; (void)n_in; (void)out_size;
    const float* hidden   = (const float*)d_in[0];
    const float* residual = (const float*)d_in[1];
    const float* alibi    = (const float*)d_in[2];
    const float* amask    = (const float*)d_in[3];
    const float* Wqkv     = (const float*)d_in[4];
    const float* bqkv     = (const float*)d_in[5];
    const float* Wd       = (const float*)d_in[6];
    const float* bd       = (const float*)d_in[7];
    float* out = (float*)d_out;

    constexpr int SMEM2 = (2*32*136 + 2*BSZ)*4;   // MT=2
    constexpr int SMEM1 = (2*32*72  + 2*BSZ)*4;   // MT=1

    cudaFuncSetAttribute(mma_gemm<0,2>, cudaFuncAttributeMaxDynamicSharedMemorySize, SMEM2);
    cudaFuncSetAttribute(mma_gemm<1,2>, cudaFuncAttributeMaxDynamicSharedMemorySize, SMEM2);
    cudaFuncSetAttribute(mma_gemm<2,1>, cudaFuncAttributeMaxDynamicSharedMemorySize, SMEM1);
    cudaFuncSetAttribute(mma_gemm<3,1>, cudaFuncAttributeMaxDynamicSharedMemorySize, SMEM1);

    // QKV projection + Q/K/V scatter
    mma_gemm<0,2><<<dim3(48,2,1), 256, SMEM2>>>(hidden, Wqkv, bqkv, nullptr, nullptr);
    // scores S = Q K^T per head
    mma_gemm<1,2><<<dim3(4,2,16), 256, SMEM2>>>(nullptr, nullptr, nullptr, nullptr, nullptr);
    // warp-per-row softmax (p, A, P2)
    softmax_k<<<512, 256>>>(alibi, amask);
    // qk importance (parity-split) + single deterministic reduce
    importance_k<<<dim3(64,16,1), 256>>>();
    reduce_imp<<<16, 256>>>(out + SQ*HIDW);
    // context = P V per head
    mma_gemm<2,1><<<dim3(1,4,16), 256, SMEM1>>>(nullptr, nullptr, nullptr, nullptr, nullptr);
    // dense + bias + residual
    mma_gemm<3,1><<<dim3(16,4,1), 256, SMEM1>>>(nullptr, Wd, bd, residual, out);
}

// round 9
// speedup vs baseline: 1.0326x; 1.0326x over previous
#include <cuda_runtime.h>
#include <cstdint>

#define SQ   256
#define NH   16
#define HD   64
#define HIDW 1024
#define LOG2E 1.4426950408889634f

static __device__ float  g_Q[NH*SQ*HD];
static __device__ float  g_K[NH*SQ*HD];
static __device__ float  g_V[NH*SQ*HD];
static __device__ float  g_S[NH*SQ*SQ];
static __device__ float  g_P[NH*SQ*SQ];
static __device__ float2 g_AP[NH*SQ*SQ];
static __device__ float  g_P2[NH*SQ];
static __device__ float  g_Ctx[SQ*HIDW];
static __device__ float  g_Part[NH*SQ*HD];     // [row][d]

__device__ __forceinline__ float ex2f(float x){ float y; asm("ex2.approx.ftz.f32 %0, %1;" : "=f"(y) : "f"(x)); return y; }
__device__ __forceinline__ float rcpf(float x){ float y; asm("rcp.approx.ftz.f32 %0, %1;" : "=f"(y) : "f"(x)); return y; }
__device__ __forceinline__ uint32_t f2tf32(float x){ uint32_t r; asm("cvt.rna.tf32.f32 %0, %1;" : "=r"(r) : "f"(x)); return r; }

__device__ __forceinline__ void mma8(float* c, const uint32_t* a, const uint32_t* b){
    asm volatile("mma.sync.aligned.m16n8k8.row.col.f32.tf32.tf32.f32 "
        "{%0,%1,%2,%3}, {%4,%5,%6,%7}, {%8,%9}, {%0,%1,%2,%3};"
        : "+f"(c[0]), "+f"(c[1]), "+f"(c[2]), "+f"(c[3])
        : "r"(a[0]), "r"(a[1]), "r"(a[2]), "r"(a[3]), "r"(b[0]), "r"(b[1]));
}

// ---------------------------------------------------------------------------
// tf32-split GEMM, double-buffered smem mainloop.
// D[(64*MT) x 64] = A[(64*MT) x KT] * B(k-major)[KT x 64]
// 3-term split (hi*hi + hi*lo + lo*hi) => fp32-grade accuracy on tensor cores.
// MODE 0: fused = hidden @ Wqkv (+bias) -> scatter Q/K/V   [B = Wqkv, direct]
// MODE 1: S[h]  = Q[h] @ K[h]^T                            [B = K, transposed at staging]
// MODE 2: Ctx   = P[h] @ V[h]                              [B = V, direct]
// MODE 3: out   = Ctx @ Wd (+bias+residual)                [B = Wd, direct]
// ---------------------------------------------------------------------------
#define BSZ (32*72)

template<int MODE, int MT>
__global__ void __launch_bounds__(256, 1) mma_gemm(const float* __restrict__ Aext,
                                                   const float* __restrict__ Bext,
                                                   const float* __restrict__ bias,
                                                   const float* __restrict__ resid,
                                                   float* __restrict__ outp)
{
    constexpr int KT  = (MODE==1) ? 64 : (MODE==2) ? 256 : 1024;
    constexpr int NK  = KT/32;
    constexpr int LDA = (MODE==1) ? 64 : (MODE==2) ? 256 : 1024;
    constexpr int LDB = (MODE==0) ? 3072 : (MODE==1) ? 64 : (MODE==2) ? 64 : 1024;
    constexpr int BM  = 64*MT;
    constexpr int AST = BM + 8;
    constexpr int ASZ = 32*AST;
    constexpr int SETSZ = 2*ASZ + 2*BSZ;

    extern __shared__ float sm[];

    const int tid = threadIdx.x, lane = tid & 31, wid = tid >> 5;
    const int wm = wid >> 1, wn = wid & 1;
    const int tig = lane & 3, gid = lane >> 2;
    const int n0 = blockIdx.x*64, m0 = blockIdx.y*BM, z = blockIdx.z;

    const float* Ag; const float* Bg;
    if constexpr (MODE==0)      { Ag = Aext;                      Bg = Bext; }
    else if constexpr (MODE==1) { Ag = g_Q + z*SQ*HD;             Bg = g_K + z*SQ*HD; }
    else if constexpr (MODE==2) { Ag = g_P + (size_t)z*SQ*SQ;     Bg = g_V + z*SQ*HD; }
    else                        { Ag = g_Ctx;                     Bg = Bext; }

    const int kqw = tid & 3, mrw = (tid >> 2) & 7, aw = tid >> 5;
    float4 pa[2*MT]; float4 pb[2]; float pbt[8];

    auto loadA = [&](int kt){
#pragma unroll
        for (int mi = 0; mi < MT; mi++)
#pragma unroll
            for (int ki = 0; ki < 2; ki++) {
                int m = aw*8 + mrw + 64*mi, kq = kqw + 4*ki;
                pa[mi*2+ki] = *(const float4*)(Ag + (size_t)(m0+m)*LDA + kt*32 + kq*4);
            }
    };
    auto loadB = [&](int kt){
        if constexpr (MODE==1) {
            int d = tid & 31, jb = (tid >> 5) * 8;
#pragma unroll
            for (int r = 0; r < 8; r++)
                pbt[r] = Bg[(size_t)(n0 + jb + r)*LDB + kt*32 + d];
        } else {
#pragma unroll
            for (int r = 0; r < 2; r++) {
                int idx = tid + 256*r, kr = idx >> 4, nq = idx & 15;
                pb[r] = *(const float4*)(Bg + (size_t)(kt*32 + kr)*LDB + n0 + nq*4);
            }
        }
    };
    auto stage = [&](int buf){
        float* Ah = sm + buf*SETSZ;
        float* Al = Ah + ASZ;
        float* Bh = Ah + 2*ASZ;
        float* Bl = Ah + 2*ASZ + BSZ;
#pragma unroll
        for (int mi = 0; mi < MT; mi++)
#pragma unroll
            for (int ki = 0; ki < 2; ki++) {
                int m = aw*8 + mrw + 64*mi, kq = kqw + 4*ki;
                int mb = m ^ ((kq & 3) << 3);
                float4 v = pa[mi*2+ki];
                float vv[4] = {v.x, v.y, v.z, v.w};
#pragma unroll
                for (int e = 0; e < 4; e++) {
                    uint32_t hb = f2tf32(vv[e]);
                    float hf = __uint_as_float(hb);
                    uint32_t lb = f2tf32(vv[e] - hf);
                    Ah[(kq*4+e)*AST + mb] = hf;
                    Al[(kq*4+e)*AST + mb] = __uint_as_float(lb);
                }
            }
        if constexpr (MODE==1) {
            int d = tid & 31, jb = (tid >> 5) * 8;
            int C = ((d >> 2) & 3) << 3;
#pragma unroll
            for (int r = 0; r < 8; r++) {
                uint32_t hb = f2tf32(pbt[r]);
                float hf = __uint_as_float(hb);
                uint32_t lb = f2tf32(pbt[r] - hf);
                int off = d*72 + ((jb + r) ^ C);
                Bh[off] = hf; Bl[off] = __uint_as_float(lb);
            }
        } else {
#pragma unroll
            for (int r = 0; r < 2; r++) {
                int idx = tid + 256*r, kr = idx >> 4, nq = idx & 15;
                int off = kr*72 + ((nq*4) ^ (((kr >> 2) & 3) << 3));
                float4 v = pb[r];
                float4 h4, l4;
                uint32_t b;
                b = f2tf32(v.x); h4.x = __uint_as_float(b); l4.x = __uint_as_float(f2tf32(v.x - h4.x));
                b = f2tf32(v.y); h4.y = __uint_as_float(b); l4.y = __uint_as_float(f2tf32(v.y - h4.y));
                b = f2tf32(v.z); h4.z = __uint_as_float(b); l4.z = __uint_as_float(f2tf32(v.z - h4.z));
                b = f2tf32(v.w); h4.w = __uint_as_float(b); l4.w = __uint_as_float(f2tf32(v.w - h4.w));
                *(float4*)(Bh + off) = h4;
                *(float4*)(Bl + off) = l4;
            }
        }
    };

    float acc[MT][4][4];
#pragma unroll
    for (int a = 0; a < MT; a++)
#pragma unroll
        for (int b = 0; b < 4; b++)
#pragma unroll
            for (int c = 0; c < 4; c++) acc[a][b][c] = 0.f;

    auto mmaOn = [&](int buf){
        const uint32_t* Ahu = (const uint32_t*)(sm + buf*SETSZ);
        const uint32_t* Alu = Ahu + ASZ;
        const uint32_t* Bhu = Ahu + 2*ASZ;
        const uint32_t* Blu = Ahu + 2*ASZ + BSZ;
#pragma unroll
        for (int ks = 0; ks < 4; ks++) {
            uint32_t ah[MT][4], al2[MT][4], bh[4][2], bl2[4][2];
            const int kA = ks*8 + tig;
            const int C0 = ((kA >> 2) & 3) << 3;
            const int C1 = (((kA + 4) >> 2) & 3) << 3;
#pragma unroll
            for (int mt = 0; mt < MT; mt++) {
                int m = wm*(16*MT) + mt*16 + gid;
                int mxa = m ^ C0, mya = m ^ C1;
                int i0 = kA*AST, i1 = (kA+4)*AST;
                ah[mt][0]  = Ahu[i0 + mxa];       ah[mt][1]  = Ahu[i0 + (mxa ^ 8)];
                ah[mt][2]  = Ahu[i1 + mya];       ah[mt][3]  = Ahu[i1 + (mya ^ 8)];
                al2[mt][0] = Alu[i0 + mxa];       al2[mt][1] = Alu[i0 + (mxa ^ 8)];
                al2[mt][2] = Alu[i1 + mya];       al2[mt][3] = Alu[i1 + (mya ^ 8)];
            }
#pragma unroll
            for (int nt = 0; nt < 4; nt++) {
                int n = wn*32 + nt*8 + gid;
                bh[nt][0]  = Bhu[kA*72 + (n ^ C0)];
                bh[nt][1]  = Bhu[(kA+4)*72 + (n ^ C1)];
                bl2[nt][0] = Blu[kA*72 + (n ^ C0)];
                bl2[nt][1] = Blu[(kA+4)*72 + (n ^ C1)];
            }
#pragma unroll
            for (int mt = 0; mt < MT; mt++)
#pragma unroll
                for (int nt = 0; nt < 4; nt++) {
                    mma8(acc[mt][nt], ah[mt],  bh[nt]);
                    mma8(acc[mt][nt], ah[mt],  bl2[nt]);
                    mma8(acc[mt][nt], al2[mt], bh[nt]);
                }
        }
    };

    // prologue: fill buffer 0
    loadA(0); loadB(0);
    stage(0);
    __syncthreads();

    for (int kt = 0; kt < NK; kt++) {
        if (kt + 1 < NK) { loadA(kt+1); loadB(kt+1); }
        mmaOn(kt & 1);                       // HMMA+LDS on current buffer
        if (kt + 1 < NK) stage((kt+1) & 1);  // STS into alternate buffer, overlaps
        __syncthreads();
    }

#pragma unroll
    for (int mt = 0; mt < MT; mt++) {
        int m = m0 + wm*(16*MT) + mt*16 + gid;
#pragma unroll
        for (int nt = 0; nt < 4; nt++) {
            int n = n0 + wn*32 + nt*8 + tig*2;
            float c0 = acc[mt][nt][0], c1 = acc[mt][nt][1];
            float c2 = acc[mt][nt][2], c3 = acc[mt][nt][3];
            if constexpr (MODE==0) {
                float2 bb = *(const float2*)(bias + n);
                int hh = n / 192, rem = n - hh*192, wch = rem >> 6, d = rem & 63;
                float* base = (wch == 0) ? g_Q : (wch == 1) ? g_K : g_V;
                *(float2*)(base + (size_t)(hh*SQ + m)*HD + d)     = make_float2(c0 + bb.x, c1 + bb.y);
                *(float2*)(base + (size_t)(hh*SQ + m + 8)*HD + d) = make_float2(c2 + bb.x, c3 + bb.y);
            } else if constexpr (MODE==1) {
                *(float2*)(g_S + (size_t)(z*SQ + m)*SQ + n)     = make_float2(c0, c1);
                *(float2*)(g_S + (size_t)(z*SQ + m + 8)*SQ + n) = make_float2(c2, c3);
            } else if constexpr (MODE==2) {
                *(float2*)(g_Ctx + (size_t)m*HIDW + z*HD + n)       = make_float2(c0, c1);
                *(float2*)(g_Ctx + (size_t)(m + 8)*HIDW + z*HD + n) = make_float2(c2, c3);
            } else {
                float2 bb = *(const float2*)(bias + n);
                float2 r0 = *(const float2*)(resid + (size_t)m*HIDW + n);
                float2 r1 = *(const float2*)(resid + (size_t)(m + 8)*HIDW + n);
                *(float2*)(outp + (size_t)m*HIDW + n)       = make_float2(c0 + bb.x + r0.x, c1 + bb.y + r0.y);
                *(float2*)(outp + (size_t)(m + 8)*HIDW + n) = make_float2(c2 + bb.x + r1.x, c3 + bb.y + r1.y);
            }
        }
    }
}

// ---------------------------------------------------------------------------
// Warp-per-row softmax: 8 warps/block, lane owns 8 j's, shfl-only reductions.
// Outputs p, A_j = exp(S/64) (masked), P2 = sum p^2.
// ---------------------------------------------------------------------------
__global__ void __launch_bounds__(256) softmax_k(const float* __restrict__ alibi,
                                                 const float* __restrict__ mask)
{
    const int w = threadIdx.x >> 5, ln = threadIdx.x & 31;
    const int row = blockIdx.x*8 + w;
    const int h = row >> 8, i = row & 255;
    const int j0 = ln*8;

    float4 s0 = *(const float4*)(g_S + (size_t)row*SQ + j0);
    float4 s1 = *(const float4*)(g_S + (size_t)row*SQ + j0 + 4);
    float4 a0 = *(const float4*)(alibi + h*SQ + j0);
    float4 a1 = *(const float4*)(alibi + h*SQ + j0 + 4);
    float4 k0 = *(const float4*)(mask + (size_t)i*SQ + j0);
    float4 k1 = *(const float4*)(mask + (size_t)i*SQ + j0 + 4);

    float sv[8] = {s0.x, s0.y, s0.z, s0.w, s1.x, s1.y, s1.z, s1.w};
    float al[8] = {a0.x, a0.y, a0.z, a0.w, a1.x, a1.y, a1.z, a1.w};
    float mk[8] = {k0.x, k0.y, k0.z, k0.w, k1.x, k1.y, k1.z, k1.w};

    float sc[8];
#pragma unroll
    for (int t = 0; t < 8; t++) sc[t] = fmaf(0.125f, sv[t], al[t]) + mk[t];

    float mx = sc[0];
#pragma unroll
    for (int t = 1; t < 8; t++) mx = fmaxf(mx, sc[t]);
#pragma unroll
    for (int o = 16; o; o >>= 1) mx = fmaxf(mx, __shfl_xor_sync(0xffffffffu, mx, o));

    float e[8], tot = 0.f;
#pragma unroll
    for (int t = 0; t < 8; t++) { e[t] = ex2f((sc[t] - mx) * LOG2E); tot += e[t]; }
#pragma unroll
    for (int o = 16; o; o >>= 1) tot += __shfl_xor_sync(0xffffffffu, tot, o);

    float iz = rcpf(tot);
    float p[8];
#pragma unroll
    for (int t = 0; t < 8; t++) p[t] = e[t] * iz;

    *(float4*)(g_P + (size_t)row*SQ + j0)     = make_float4(p[0], p[1], p[2], p[3]);
    *(float4*)(g_P + (size_t)row*SQ + j0 + 4) = make_float4(p[4], p[5], p[6], p[7]);

    float av[8];
#pragma unroll
    for (int t = 0; t < 8; t++) av[t] = (j0 + t <= i) ? ex2f(sv[t] * (LOG2E/64.f)) : 0.f;

    float4* app = (float4*)(g_AP + (size_t)row*SQ);
    app[ln*4 + 0] = make_float4(av[0], p[0], av[1], p[1]);
    app[ln*4 + 1] = make_float4(av[2], p[2], av[3], p[3]);
    app[ln*4 + 2] = make_float4(av[4], p[4], av[5], p[5]);
    app[ln*4 + 3] = make_float4(av[6], p[6], av[7], p[7]);

    float pq = 0.f;
#pragma unroll
    for (int t = 0; t < 8; t++) pq = fmaf(p[t], p[t], pq);
#pragma unroll
    for (int o = 16; o; o >>= 1) pq += __shfl_xor_sync(0xffffffffu, pq, o);
    if (ln == 0) g_P2[row] = pq;
}

// ---------------------------------------------------------------------------
// qk_importance hybrid: block = (pair(i1,255-i1), h), 256 threads =
// 2 j-splits x (2 rows x 64 d).  Each split keeps the unroll-4 float4 body
// (8 independent ex2 chains) over j-blocks [8k+4*par, 8k+4*par+4).
// Bounds rounded up to x8 exploiting g_AP[.].x == 0 for masked j.
// Partials combined in smem in fixed order (deterministic).
// ---------------------------------------------------------------------------
__global__ void __launch_bounds__(256) importance_k()
{
    __shared__ float s_red[6][2][128];
    const int tid = threadIdx.x;
    const int d   = tid & 63;
    const int p2  = (tid >> 6) & 1;
    const int par = tid >> 7;                 // j-split 0/1
    const int h   = blockIdx.y;
    const int i1  = blockIdx.x + 64*p2;       // 0..127
    const int i2  = 255 - i1;                 // 128..255
    const int row1 = h*SQ + i1, row2 = h*SQ + i2;

    const float qe1 = g_Q[row1*HD + d] * (-LOG2E/64.f);
    const float qe2 = g_Q[row2*HD + d] * (-LOG2E/64.f);
    const float*  kp  = g_K + h*SQ*HD + d;
    const float4* ap1 = (const float4*)(g_AP + (size_t)row1*SQ);
    const float4* ap2 = (const float4*)(g_AP + (size_t)row2*SQ);

    float Z1=0.f, W21=0.f, WP1=0.f, Z2=0.f, W22=0.f, WP2=0.f;
    const int e1 = (i1 + 8) & ~7;             // mult of 8, <= 128
    const int e2 = (i2 + 8) & ~7;             // mult of 8, <= 256
    int j = 4*par;
    for (; j < e1; j += 8) {                  // phase 1: both rows, j..j+3
        float k0 = kp[(j+0)*HD], k1 = kp[(j+1)*HD];
        float k2 = kp[(j+2)*HD], k3 = kp[(j+3)*HD];
        float4 u0 = ap1[(j>>1)], u1 = ap1[(j>>1)+1];
        float4 v0 = ap2[(j>>1)], v1 = ap2[(j>>1)+1];
        float E0 = ex2f(qe1*k0), E1 = ex2f(qe1*k1), E2 = ex2f(qe1*k2), E3 = ex2f(qe1*k3);
        float F0 = ex2f(qe2*k0), F1 = ex2f(qe2*k1), F2 = ex2f(qe2*k2), F3 = ex2f(qe2*k3);
        float w;
        w = u0.x*E0; Z1 += w; W21 = fmaf(w,w,W21); WP1 = fmaf(w,u0.y,WP1);
        w = u0.z*E1; Z1 += w; W21 = fmaf(w,w,W21); WP1 = fmaf(w,u0.w,WP1);
        w = u1.x*E2; Z1 += w; W21 = fmaf(w,w,W21); WP1 = fmaf(w,u1.y,WP1);
        w = u1.z*E3; Z1 += w; W21 = fmaf(w,w,W21); WP1 = fmaf(w,u1.w,WP1);
        w = v0.x*F0; Z2 += w; W22 = fmaf(w,w,W22); WP2 = fmaf(w,v0.y,WP2);
        w = v0.z*F1; Z2 += w; W22 = fmaf(w,w,W22); WP2 = fmaf(w,v0.w,WP2);
        w = v1.x*F2; Z2 += w; W22 = fmaf(w,w,W22); WP2 = fmaf(w,v1.y,WP2);
        w = v1.z*F3; Z2 += w; W22 = fmaf(w,w,W22); WP2 = fmaf(w,v1.w,WP2);
    }
    for (; j < e2; j += 8) {                  // phase 2: row2 only
        float k0 = kp[(j+0)*HD], k1 = kp[(j+1)*HD];
        float k2 = kp[(j+2)*HD], k3 = kp[(j+3)*HD];
        float4 v0 = ap2[(j>>1)], v1 = ap2[(j>>1)+1];
        float F0 = ex2f(qe2*k0), F1 = ex2f(qe2*k1), F2 = ex2f(qe2*k2), F3 = ex2f(qe2*k3);
        float w;
        w = v0.x*F0; Z2 += w; W22 = fmaf(w,w,W22); WP2 = fmaf(w,v0.y,WP2);
        w = v0.z*F1; Z2 += w; W22 = fmaf(w,w,W22); WP2 = fmaf(w,v0.w,WP2);
        w = v1.x*F2; Z2 += w; W22 = fmaf(w,w,W22); WP2 = fmaf(w,v1.y,WP2);
        w = v1.z*F3; Z2 += w; W22 = fmaf(w,w,W22); WP2 = fmaf(w,v1.w,WP2);
    }

    const int slot = p2*64 + d;
    s_red[0][par][slot] = Z1;  s_red[1][par][slot] = W21; s_red[2][par][slot] = WP1;
    s_red[3][par][slot] = Z2;  s_red[4][par][slot] = W22; s_red[5][par][slot] = WP2;
    __syncthreads();
    if (tid < 128) {
        float Zt1 = s_red[0][0][tid] + s_red[0][1][tid];
        float Wt1 = s_red[1][0][tid] + s_red[1][1][tid];
        float Pt1 = s_red[2][0][tid] + s_red[2][1][tid];
        float Zt2 = s_red[3][0][tid] + s_red[3][1][tid];
        float Wt2 = s_red[4][0][tid] + s_red[4][1][tid];
        float Pt2 = s_red[5][0][tid] + s_red[5][1][tid];
        const int dd = tid & 63;
        const int r1 = h*SQ + (blockIdx.x + 64*(tid >> 6));
        const int r2 = h*SQ + 255 - (blockIdx.x + 64*(tid >> 6));
        float iz1 = rcpf(Zt1), iz2 = rcpf(Zt2);
        g_Part[r1*HD + dd] = fmaf(Wt1*iz1, iz1, -2.f*Pt1*iz1) + g_P2[r1];
        g_Part[r2*HD + dd] = fmaf(Wt2*iz2, iz2, -2.f*Pt2*iz2) + g_P2[r2];
    }
}

// Single-kernel deterministic reduction: block per head.
__global__ void __launch_bounds__(256) reduce_imp(float* __restrict__ imp)
{
    __shared__ float s[4][64];
    const int h = blockIdx.x, rr = threadIdx.x >> 6, d = threadIdx.x & 63;
    float s0 = 0.f;
#pragma unroll 8
    for (int r = 0; r < 64; ++r)
        s0 += g_Part[(h*SQ + rr*64 + r)*HD + d];
    s[rr][d] = s0;
    __syncthreads();
    if (threadIdx.x < 64)
        imp[h*64 + threadIdx.x] = (s[0][threadIdx.x] + s[1][threadIdx.x])
                                + (s[2][threadIdx.x] + s[3][threadIdx.x]);
}

// ---------------------------------------------------------------------------
extern "C" void kernel_launch(void* const* d_in, const int* in_sizes, int n_in,
                              void* d_out, int out_size)
{
    (void)in_sizes; (void)n_in; (void)out_size;
    const float* hidden   = (const float*)d_in[0];
    const float* residual = (const float*)d_in[1];
    const float* alibi    = (const float*)d_in[2];
    const float* amask    = (const float*)d_in[3];
    const float* Wqkv     = (const float*)d_in[4];
    const float* bqkv     = (const float*)d_in[5];
    const float* Wd       = (const float*)d_in[6];
    const float* bd       = (const float*)d_in[7];
    float* out = (float*)d_out;

    constexpr int SMEM2 = 2*(2*32*136 + 2*BSZ)*4;   // MT=2 double-buffered: 106496
    constexpr int SMEM1 = 2*(2*32*72  + 2*BSZ)*4;   // MT=1 double-buffered:  73728

    cudaFuncSetAttribute(mma_gemm<0,2>, cudaFuncAttributeMaxDynamicSharedMemorySize, SMEM2);
    cudaFuncSetAttribute(mma_gemm<1,2>, cudaFuncAttributeMaxDynamicSharedMemorySize, SMEM2);
    cudaFuncSetAttribute(mma_gemm<2,1>, cudaFuncAttributeMaxDynamicSharedMemorySize, SMEM1);
    cudaFuncSetAttribute(mma_gemm<3,1>, cudaFuncAttributeMaxDynamicSharedMemorySize, SMEM1);

    // QKV projection + Q/K/V scatter
    mma_gemm<0,2><<<dim3(48,2,1), 256, SMEM2>>>(hidden, Wqkv, bqkv, nullptr, nullptr);
    // scores S = Q K^T per head
    mma_gemm<1,2><<<dim3(4,2,16), 256, SMEM2>>>(nullptr, nullptr, nullptr, nullptr, nullptr);
    // warp-per-row softmax (p, A, P2)
    softmax_k<<<512, 256>>>(alibi, amask);
    // qk importance (hybrid split) + single deterministic reduce
    importance_k<<<dim3(64,16,1), 256>>>();
    reduce_imp<<<16, 256>>>(out + SQ*HIDW);
    // context = P V per head
    mma_gemm<2,1><<<dim3(1,4,16), 256, SMEM1>>>(nullptr, nullptr, nullptr, nullptr, nullptr);
    // dense + bias + residual
    mma_gemm<3,1><<<dim3(16,4,1), 256, SMEM1>>>(nullptr, Wd, bd, residual, out);
}